// round 15
// baseline (speedup 1.0000x reference)
#include <cuda_runtime.h>
#include <cuda_bf16.h>
#include <math.h>

#define BB 8
#define LL 2048
#define DM 512
#define DI 1024
#define DS 16
#define DTR 32
#define CC 32          // time chunks
#define TT 64          // chunk length
#define EPSV 1e-5f

// ---------------- scratch (device globals; no runtime allocation) -------------
__device__ float g_scal[8];                 // mw, mb, mww, mwb, mbb
__device__ int   g_fastA;
__device__ float g_p1[2 * DI];
__device__ float g_p2[2 * DI];
__device__ float g_p3[2 * DI];
__device__ float g_weff[DI];
__device__ float g_A[DI * DS];              // -exp(A_log)
__device__ float g_a[BB * LL];
__device__ float g_c[BB * LL];
__device__ float g_xc[(size_t)BB * DI * LL];   // [b][d][t] conv+silu output
__device__ float g_dtl[BB * LL * DTR];         // [b][t][32] dt low-rank
__device__ float g_Bt[BB * DS * LL];           // [b][s][t]
__device__ float g_Ct[BB * DS * LL];           // [b][s][t]
__device__ float g_dtT[(size_t)BB * DI * LL];  // [b][d][t] softplus(dt)
__device__ float g_hF[(size_t)BB * CC * DI * DS];   // chunk-local final states
__device__ float g_Ssum[BB * CC * DI];              // chunk dt sums
__device__ float g_H[(size_t)BB * CC * DI * DS];    // incoming state per chunk
__device__ float g_red[4 * BB * LL];                // d-group partial sums

// scalar power tree: p[s] = e1^(s+1)
#define POWTREE(p, e1)                                                          \
    {                                                                           \
        p[0] = (e1);  p[1] = p[0] * p[0];  p[2] = p[1] * p[0];                  \
        p[3] = p[1] * p[1];  p[4] = p[3] * p[0];  p[5] = p[3] * p[1];           \
        p[6] = p[3] * p[2];  p[7] = p[3] * p[3];  p[8] = p[7] * p[0];           \
        p[9] = p[7] * p[1];  p[10] = p[7] * p[2]; p[11] = p[7] * p[3];          \
        p[12] = p[7] * p[4]; p[13] = p[7] * p[5]; p[14] = p[7] * p[6];          \
        p[15] = p[7] * p[7];                                                    \
    }

// ---------------- K1: moments of W_in1 / b_in1 --------------------------------
__global__ void k_stats(const float* __restrict__ w, const float* __restrict__ b) {
    __shared__ float sh[5][16];
    int tid = threadIdx.x;               // 512 threads
    float wv = w[tid], bv = b[tid];
    float v[5] = {wv, bv, wv * wv, wv * bv, bv * bv};
#pragma unroll
    for (int j = 0; j < 5; j++) {
#pragma unroll
        for (int o = 16; o > 0; o >>= 1) v[j] += __shfl_xor_sync(0xffffffffu, v[j], o);
    }
    if ((tid & 31) == 0) {
#pragma unroll
        for (int j = 0; j < 5; j++) sh[j][tid >> 5] = v[j];
    }
    if (tid == 0) g_fastA = 1;
    __syncthreads();
    if (tid < 5) {
        float s = 0.f;
#pragma unroll
        for (int k = 0; k < 16; k++) s += sh[tid][k];
        g_scal[tid] = s * (1.0f / DM);
    }
}

// ---------------- K2: p-vectors, w_eff, A, per-token a/c ----------------------
__global__ void k_prep(const float* __restrict__ Win1, const float* __restrict__ bin1,
                       const float* __restrict__ lng,  const float* __restrict__ lnb,
                       const float* __restrict__ Wxz,  const float* __restrict__ Wom,
                       const float* __restrict__ Wout, const float* __restrict__ Alog,
                       const float* __restrict__ x) {
    int idx = blockIdx.x * 256 + threadIdx.x;
    float mw = g_scal[0], mb = g_scal[1], mww = g_scal[2], mwb = g_scal[3], mbb = g_scal[4];
    if (idx < 4 * 2 * DI) {
        int col  = idx >> 2;              // output column 0..2047
        int part = idx & 3;               // d-range split
        float s1 = 0.f, s2 = 0.f, s3 = 0.f;
        for (int d = part * 128; d < part * 128 + 128; d++) {
            float gd = lng[d];
            float u = (Win1[d] - mw) * gd;
            float v = (bin1[d] - mb) * gd;
            float wv = Wxz[d * (2 * DI) + col];
            s1 = fmaf(u, wv, s1);
            s2 = fmaf(v, wv, s2);
            s3 = fmaf(lnb[d], wv, s3);
        }
        s1 += __shfl_xor_sync(0xffffffffu, s1, 1); s1 += __shfl_xor_sync(0xffffffffu, s1, 2);
        s2 += __shfl_xor_sync(0xffffffffu, s2, 1); s2 += __shfl_xor_sync(0xffffffffu, s2, 2);
        s3 += __shfl_xor_sync(0xffffffffu, s3, 1); s3 += __shfl_xor_sync(0xffffffffu, s3, 2);
        if (part == 0) { g_p1[col] = s1; g_p2[col] = s2; g_p3[col] = s3; }
    } else if (idx < 8192 + DI) {
        int j = idx - 8192;
        float s = 0.f;
        for (int m = 0; m < DM; m++) s = fmaf(Wom[j * DM + m], Wout[m], s);
        g_weff[j] = s;
    } else if (idx < 8192 + DI + DI * DS) {
        int i2 = idx - 8192 - DI;
        float av = -expf(Alog[i2]);
        g_A[i2] = av;
        int s = i2 & (DS - 1);
        float expect = -(float)(s + 1);
        if (fabsf(av - expect) > 1e-4f * (float)(s + 1)) atomicAnd(&g_fastA, 0);
    } else if (idx < 8192 + DI + DI * DS + BB * LL) {
        int i2 = idx - 8192 - DI - DI * DS;
        float xv = x[i2];
        float varw = mww - mw * mw;
        float cwb  = mwb - mw * mb;
        float varb = mbb - mb * mb;
        float var  = fmaf(xv * xv, varw, fmaf(2.0f * xv, cwb, varb));
        float s    = rsqrtf(var + EPSV);
        g_a[i2] = xv * s;
        g_c[i2] = s;
    }
}

// ---------------- K3: conv + silu -> xc (32B buffered stores) -----------------
__global__ __launch_bounds__(256) void k_xc(const float* __restrict__ convw,
                                            const float* __restrict__ convb) {
    int bx = blockIdx.x;                      // 1024 blocks
    int b   = bx >> 7;
    int rem = bx & 127;
    int t0  = (rem >> 2) * 64;
    int d   = (rem & 3) * 256 + threadIdx.x;

    __shared__ float shA[67], shC[67];
    if (threadIdx.x < 67) {
        int gt = t0 - 3 + (int)threadIdx.x;
        shA[threadIdx.x] = (gt >= 0) ? g_a[b * LL + gt] : 0.f;
        shC[threadIdx.x] = (gt >= 0) ? g_c[b * LL + gt] : 0.f;
    }
    float p1d = g_p1[d], p2d = g_p2[d], p3d = g_p3[d];
    float cw0 = convw[d * 4 + 0], cw1 = convw[d * 4 + 1];
    float cw2 = convw[d * 4 + 2], cw3 = convw[d * 4 + 3];
    float cb = convb[d];
    float cwsum = cw0 + cw1 + cw2 + cw3;
    __syncthreads();

    float* xop = g_xc + ((size_t)(b * DI + d)) * LL + t0;
    float xb[8];
#pragma unroll 8
    for (int tt = 0; tt < 64; tt++) {
        int t = t0 + tt;
        float a0 = shA[tt], a1 = shA[tt + 1], a2 = shA[tt + 2], a3 = shA[tt + 3];
        float c0 = shC[tt], c1 = shC[tt + 1], c2 = shC[tt + 2], c3 = shC[tt + 3];
        float sa = fmaf(a0, cw0, fmaf(a1, cw1, fmaf(a2, cw2, a3 * cw3)));
        float sc = fmaf(c0, cw0, fmaf(c1, cw1, fmaf(c2, cw2, c3 * cw3)));
        float sw;
        if (t >= 3) sw = cwsum;
        else { sw = cw3; if (t >= 1) sw += cw2; if (t >= 2) sw += cw1; }
        float pre = fmaf(p1d, sa, fmaf(p2d, sc, fmaf(p3d, sw, cb)));
        xb[tt & 7] = __fdividef(pre, 1.0f + __expf(-pre));
        if ((tt & 7) == 7) {
            *(float4*)(xop + tt - 7) = make_float4(xb[0], xb[1], xb[2], xb[3]);
            *(float4*)(xop + tt - 3) = make_float4(xb[4], xb[5], xb[6], xb[7]);
        }
    }
}

// ---------------- K4: xc @ W_xp (double-buffered tiles) -----------------------
__global__ __launch_bounds__(256) void k_proj(const float* __restrict__ Wxp) {
    int blk = blockIdx.x;                    // 256 blocks
    int b  = blk >> 5;
    int t0 = (blk & 31) * 64;
    __shared__ float At[2][32][68];
    __shared__ float Bt_[2][32][64];
    int tid = threadIdx.x;
    int tx = tid & 15, ty = tid >> 4;
    float acc[4][4];
#pragma unroll
    for (int i = 0; i < 4; i++)
#pragma unroll
        for (int j = 0; j < 4; j++) acc[i][j] = 0.f;

    int akk0 = tid >> 4,          at40 = tid & 15;
    int akk1 = (tid + 256) >> 4,  at41 = tid & 15;
    const size_t xcb = (size_t)(b * DI) * LL + t0;

    float4 ra0 = *(const float4*)(g_xc + xcb + (size_t)(akk0)*LL + at40 * 4);
    float4 ra1 = *(const float4*)(g_xc + xcb + (size_t)(akk1)*LL + at41 * 4);
    float4 rb0 = *(const float4*)(Wxp + (size_t)(akk0)*64 + at40 * 4);
    float4 rb1 = *(const float4*)(Wxp + (size_t)(akk1)*64 + at41 * 4);
    *(float4*)&At[0][akk0][at40 * 4] = ra0;
    *(float4*)&At[0][akk1][at41 * 4] = ra1;
    *(float4*)&Bt_[0][akk0][at40 * 4] = rb0;
    *(float4*)&Bt_[0][akk1][at41 * 4] = rb1;
    __syncthreads();

    for (int kt = 0; kt < 32; kt++) {
        int cur = kt & 1;
        if (kt < 31) {
            int k0 = (kt + 1) * 32;
            ra0 = *(const float4*)(g_xc + xcb + (size_t)(k0 + akk0) * LL + at40 * 4);
            ra1 = *(const float4*)(g_xc + xcb + (size_t)(k0 + akk1) * LL + at41 * 4);
            rb0 = *(const float4*)(Wxp + (size_t)(k0 + akk0) * 64 + at40 * 4);
            rb1 = *(const float4*)(Wxp + (size_t)(k0 + akk1) * 64 + at41 * 4);
        }
#pragma unroll
        for (int kk = 0; kk < 32; kk++) {
            float4 bv = *(float4*)&Bt_[cur][kk][tx * 4];
            float4 av = *(float4*)&At[cur][kk][ty * 4];
            acc[0][0] = fmaf(av.x, bv.x, acc[0][0]);
            acc[0][1] = fmaf(av.x, bv.y, acc[0][1]);
            acc[0][2] = fmaf(av.x, bv.z, acc[0][2]);
            acc[0][3] = fmaf(av.x, bv.w, acc[0][3]);
            acc[1][0] = fmaf(av.y, bv.x, acc[1][0]);
            acc[1][1] = fmaf(av.y, bv.y, acc[1][1]);
            acc[1][2] = fmaf(av.y, bv.z, acc[1][2]);
            acc[1][3] = fmaf(av.y, bv.w, acc[1][3]);
            acc[2][0] = fmaf(av.z, bv.x, acc[2][0]);
            acc[2][1] = fmaf(av.z, bv.y, acc[2][1]);
            acc[2][2] = fmaf(av.z, bv.z, acc[2][2]);
            acc[2][3] = fmaf(av.z, bv.w, acc[2][3]);
            acc[3][0] = fmaf(av.w, bv.x, acc[3][0]);
            acc[3][1] = fmaf(av.w, bv.y, acc[3][1]);
            acc[3][2] = fmaf(av.w, bv.z, acc[3][2]);
            acc[3][3] = fmaf(av.w, bv.w, acc[3][3]);
        }
        if (kt < 31) {
            int nxt = cur ^ 1;
            *(float4*)&At[nxt][akk0][at40 * 4] = ra0;
            *(float4*)&At[nxt][akk1][at41 * 4] = ra1;
            *(float4*)&Bt_[nxt][akk0][at40 * 4] = rb0;
            *(float4*)&Bt_[nxt][akk1][at41 * 4] = rb1;
        }
        __syncthreads();
    }
#pragma unroll
    for (int i = 0; i < 4; i++) {
        int t = t0 + ty * 4 + i;
        if (tx < 8) {
            *(float4*)(g_dtl + ((size_t)(b * LL + t)) * DTR + tx * 4) =
                make_float4(acc[i][0], acc[i][1], acc[i][2], acc[i][3]);
        } else {
#pragma unroll
            for (int j = 0; j < 4; j++) {
                int n = tx * 4 + j;
                if (n < 48) g_Bt[((size_t)(b * DS + n - 32)) * LL + t] = acc[i][j];
                else        g_Ct[((size_t)(b * DS + n - 48)) * LL + t] = acc[i][j];
            }
        }
    }
}

// ---------------- K5: softplus(dt_low @ W_dt + b_dt) -> dtT [b][d][t] ---------
__global__ __launch_bounds__(256) void k_dt(const float* __restrict__ Wdt,
                                            const float* __restrict__ bdt) {
    int blk = blockIdx.x;                    // 1024 blocks
    int b   = blk >> 7;
    int rem = blk & 127;
    int t0  = (rem >> 2) * 64;
    int d   = (rem & 3) * 256 + threadIdx.x;
    __shared__ float sh[64][32];
    const float4* src = (const float4*)(g_dtl + ((size_t)(b * LL + t0)) * DTR);
    float4* dst = (float4*)&sh[0][0];
    for (int i = threadIdx.x; i < 512; i += 256) dst[i] = src[i];
    float wreg[32];
#pragma unroll
    for (int k = 0; k < 32; k++) wreg[k] = Wdt[(size_t)k * DI + d];
    float bd = bdt[d];
    __syncthreads();
    float* op = g_dtT + ((size_t)(b * DI + d)) * LL + t0;
    float buf[8];
#pragma unroll 8
    for (int tt = 0; tt < 64; tt++) {
        float acc = bd;
#pragma unroll
        for (int k4 = 0; k4 < 8; k4++) {
            float4 v = *(const float4*)&sh[tt][k4 * 4];
            acc = fmaf(v.x, wreg[k4 * 4 + 0], acc);
            acc = fmaf(v.y, wreg[k4 * 4 + 1], acc);
            acc = fmaf(v.z, wreg[k4 * 4 + 2], acc);
            acc = fmaf(v.w, wreg[k4 * 4 + 3], acc);
        }
        buf[tt & 7] = (acc > 20.0f) ? acc : log1pf(__expf(acc));
        if ((tt & 7) == 7) {
            *(float4*)(op + tt - 7) = make_float4(buf[0], buf[1], buf[2], buf[3]);
            *(float4*)(op + tt - 3) = make_float4(buf[4], buf[5], buf[6], buf[7]);
        }
    }
}

// ---------------- K6a: chunk-local scan (prefetched stream) -------------------
__global__ __launch_bounds__(256) void k_scan1(void) {
    int blk = blockIdx.x;                // 1024 = b(8) x c(32) x dg(4)
    int b  = blk >> 7;
    int c  = (blk >> 2) & 31;
    int dg = blk & 3;
    int tid = threadIdx.x;
    int d  = dg * 256 + tid;
    int t0 = c * TT;

    __shared__ float Bs[TT * DS];        // [t][s]
    for (int i = tid; i < TT * DS; i += 256) {
        int s = i >> 6, t = i & 63;
        Bs[t * DS + s] = g_Bt[((size_t)b * DS + s) * LL + t0 + t];
    }
    __syncthreads();

    const float4* dtp = (const float4*)(g_dtT + ((size_t)b * DI + d) * LL + t0);
    const float4* xcp = (const float4*)(g_xc  + ((size_t)b * DI + d) * LL + t0);
    int fast = g_fastA;
    float Areg[16];
    if (!fast) {
#pragma unroll
        for (int s = 0; s < 16; s++) Areg[s] = g_A[d * DS + s];
    }
    float h[16];
#pragma unroll
    for (int s = 0; s < 16; s++) h[s] = 0.f;
    float S = 0.f;

    float4 dtv = dtp[0], xcv = xcp[0];
#pragma unroll 4
    for (int q = 0; q < TT / 4; q++) {
        float4 dtn, xcn;
        if (q < TT / 4 - 1) { dtn = dtp[q + 1]; xcn = xcp[q + 1]; }
#pragma unroll
        for (int u = 0; u < 4; u++) {
            float dtc = (u == 0) ? dtv.x : (u == 1) ? dtv.y : (u == 2) ? dtv.z : dtv.w;
            float xcc = (u == 0) ? xcv.x : (u == 1) ? xcv.y : (u == 2) ? xcv.z : xcv.w;
            int t = q * 4 + u;
            S += dtc;
            float dx = dtc * xcc;
            float p[16];
            if (fast) {
                float e1 = __expf(-dtc);
                POWTREE(p, e1)
            } else {
#pragma unroll
                for (int s = 0; s < 16; s++) p[s] = __expf(dtc * Areg[s]);
            }
            const float4* bp = (const float4*)&Bs[t * DS];
            float4 b0 = bp[0], b1 = bp[1], b2 = bp[2], b3 = bp[3];
            h[0]  = fmaf(h[0],  p[0],  dx * b0.x);
            h[1]  = fmaf(h[1],  p[1],  dx * b0.y);
            h[2]  = fmaf(h[2],  p[2],  dx * b0.z);
            h[3]  = fmaf(h[3],  p[3],  dx * b0.w);
            h[4]  = fmaf(h[4],  p[4],  dx * b1.x);
            h[5]  = fmaf(h[5],  p[5],  dx * b1.y);
            h[6]  = fmaf(h[6],  p[6],  dx * b1.z);
            h[7]  = fmaf(h[7],  p[7],  dx * b1.w);
            h[8]  = fmaf(h[8],  p[8],  dx * b2.x);
            h[9]  = fmaf(h[9],  p[9],  dx * b2.y);
            h[10] = fmaf(h[10], p[10], dx * b2.z);
            h[11] = fmaf(h[11], p[11], dx * b2.w);
            h[12] = fmaf(h[12], p[12], dx * b3.x);
            h[13] = fmaf(h[13], p[13], dx * b3.y);
            h[14] = fmaf(h[14], p[14], dx * b3.z);
            h[15] = fmaf(h[15], p[15], dx * b3.w);
        }
        dtv = dtn; xcv = xcn;
    }
    float* o = g_hF + (((size_t)b * CC + c) * DI + d) * DS;
    *(float4*)(o + 0)  = make_float4(h[0], h[1], h[2], h[3]);
    *(float4*)(o + 4)  = make_float4(h[4], h[5], h[6], h[7]);
    *(float4*)(o + 8)  = make_float4(h[8], h[9], h[10], h[11]);
    *(float4*)(o + 12) = make_float4(h[12], h[13], h[14], h[15]);
    g_Ssum[((size_t)b * CC + c) * DI + d] = S;
}

// ---------------- K6b: propagate states across chunks ------------------------
__global__ __launch_bounds__(256) void k_scan2(void) {
    int idx = blockIdx.x * 256 + threadIdx.x;     // < 8192
    int b = idx >> 10;
    int d = idx & (DI - 1);
    int fast = g_fastA;
    float Areg[16];
    if (!fast) {
#pragma unroll
        for (int s = 0; s < 16; s++) Areg[s] = g_A[d * DS + s];
    }
    float H[16];
#pragma unroll
    for (int s = 0; s < 16; s++) H[s] = 0.f;
#pragma unroll 4
    for (int c = 0; c < CC; c++) {
        float* o = g_H + (((size_t)b * CC + c) * DI + d) * DS;
        *(float4*)(o + 0)  = make_float4(H[0], H[1], H[2], H[3]);
        *(float4*)(o + 4)  = make_float4(H[4], H[5], H[6], H[7]);
        *(float4*)(o + 8)  = make_float4(H[8], H[9], H[10], H[11]);
        *(float4*)(o + 12) = make_float4(H[12], H[13], H[14], H[15]);
        float S = g_Ssum[((size_t)b * CC + c) * DI + d];
        float p[16];
        if (fast) {
            float e1 = __expf(-S);
            POWTREE(p, e1)
        } else {
#pragma unroll
            for (int s = 0; s < 16; s++) p[s] = __expf(S * Areg[s]);
        }
        const float* f = g_hF + (((size_t)b * CC + c) * DI + d) * DS;
        float4 f0 = *(const float4*)(f + 0), f1 = *(const float4*)(f + 4);
        float4 f2 = *(const float4*)(f + 8), f3 = *(const float4*)(f + 12);
        H[0]  = fmaf(H[0],  p[0],  f0.x);  H[1]  = fmaf(H[1],  p[1],  f0.y);
        H[2]  = fmaf(H[2],  p[2],  f0.z);  H[3]  = fmaf(H[3],  p[3],  f0.w);
        H[4]  = fmaf(H[4],  p[4],  f1.x);  H[5]  = fmaf(H[5],  p[5],  f1.y);
        H[6]  = fmaf(H[6],  p[6],  f1.z);  H[7]  = fmaf(H[7],  p[7],  f1.w);
        H[8]  = fmaf(H[8],  p[8],  f2.x);  H[9]  = fmaf(H[9],  p[9],  f2.y);
        H[10] = fmaf(H[10], p[10], f2.z);  H[11] = fmaf(H[11], p[11], f2.w);
        H[12] = fmaf(H[12], p[12], f3.x);  H[13] = fmaf(H[13], p[13], f3.y);
        H[14] = fmaf(H[14], p[14], f3.z);  H[15] = fmaf(H[15], p[15], f3.w);
    }
}

// ---------------- K6c: full scan + gate + fused d-reduction (prefetched) ------
__global__ __launch_bounds__(256) void k_scan3(const float* __restrict__ Dskip) {
    int blk = blockIdx.x;                // 1024 = b(8) x c(32) x dg(4)
    int b  = blk >> 7;
    int c  = (blk >> 2) & 31;
    int dg = blk & 3;
    int tid = threadIdx.x;
    int d  = dg * 256 + tid;
    int t0 = c * TT;
    int lane = tid & 31;
    int warp = tid >> 5;

    __shared__ float Bs[TT * DS];
    __shared__ float Cs[TT * DS];
    __shared__ float ash[TT], csh[TT];
    __shared__ float sred[8][TT];
    for (int i = tid; i < 2 * TT * DS; i += 256) {
        int half = i >> 10;               // 0 = B, 1 = C
        int j = i & 1023;
        int s = j >> 6, t = j & 63;
        float v = half ? g_Ct[((size_t)b * DS + s) * LL + t0 + t]
                       : g_Bt[((size_t)b * DS + s) * LL + t0 + t];
        (half ? Cs : Bs)[t * DS + s] = v;
    }
    if (tid < TT) {
        ash[tid] = g_a[b * LL + t0 + tid];
        csh[tid] = g_c[b * LL + t0 + tid];
    }
    __syncthreads();

    const float4* dtp = (const float4*)(g_dtT + ((size_t)b * DI + d) * LL + t0);
    const float4* xcp = (const float4*)(g_xc  + ((size_t)b * DI + d) * LL + t0);
    int fast = g_fastA;
    float Areg[16];
    if (!fast) {
#pragma unroll
        for (int s = 0; s < 16; s++) Areg[s] = g_A[d * DS + s];
    }
    float p1z = g_p1[DI + d], p2z = g_p2[DI + d], p3z = g_p3[DI + d];
    float we = g_weff[d];
    float Dd = Dskip[d];
    const float* Hp = g_H + (((size_t)b * CC + c) * DI + d) * DS;
    float4 H0 = *(const float4*)(Hp + 0), H1 = *(const float4*)(Hp + 4);
    float4 H2 = *(const float4*)(Hp + 8), H3 = *(const float4*)(Hp + 12);
    float h[16] = {H0.x, H0.y, H0.z, H0.w, H1.x, H1.y, H1.z, H1.w,
                   H2.x, H2.y, H2.z, H2.w, H3.x, H3.y, H3.z, H3.w};

    float4 dtv = dtp[0], xcv = xcp[0];
#pragma unroll 2
    for (int q = 0; q < TT / 4; q++) {
        float4 dtn, xcn;
        if (q < TT / 4 - 1) { dtn = dtp[q + 1]; xcn = xcp[q + 1]; }
#pragma unroll
        for (int u = 0; u < 4; u++) {
            float dtc = (u == 0) ? dtv.x : (u == 1) ? dtv.y : (u == 2) ? dtv.z : dtv.w;
            float xcc = (u == 0) ? xcv.x : (u == 1) ? xcv.y : (u == 2) ? xcv.z : xcv.w;
            int t = q * 4 + u;
            float dx = dtc * xcc;
            float p[16];
            if (fast) {
                float e1 = __expf(-dtc);
                POWTREE(p, e1)
            } else {
#pragma unroll
                for (int s = 0; s < 16; s++) p[s] = __expf(dtc * Areg[s]);
            }
            const float4* bp = (const float4*)&Bs[t * DS];
            const float4* cp = (const float4*)&Cs[t * DS];
            float4 b0 = bp[0], b1 = bp[1], b2 = bp[2], b3 = bp[3];
            float4 c0 = cp[0], c1 = cp[1], c2 = cp[2], c3 = cp[3];
            h[0]  = fmaf(h[0],  p[0],  dx * b0.x);
            h[1]  = fmaf(h[1],  p[1],  dx * b0.y);
            h[2]  = fmaf(h[2],  p[2],  dx * b0.z);
            h[3]  = fmaf(h[3],  p[3],  dx * b0.w);
            h[4]  = fmaf(h[4],  p[4],  dx * b1.x);
            h[5]  = fmaf(h[5],  p[5],  dx * b1.y);
            h[6]  = fmaf(h[6],  p[6],  dx * b1.z);
            h[7]  = fmaf(h[7],  p[7],  dx * b1.w);
            h[8]  = fmaf(h[8],  p[8],  dx * b2.x);
            h[9]  = fmaf(h[9],  p[9],  dx * b2.y);
            h[10] = fmaf(h[10], p[10], dx * b2.z);
            h[11] = fmaf(h[11], p[11], dx * b2.w);
            h[12] = fmaf(h[12], p[12], dx * b3.x);
            h[13] = fmaf(h[13], p[13], dx * b3.y);
            h[14] = fmaf(h[14], p[14], dx * b3.z);
            h[15] = fmaf(h[15], p[15], dx * b3.w);
            float y = h[0] * c0.x;
            y = fmaf(h[1],  c0.y, y);
            y = fmaf(h[2],  c0.z, y);
            y = fmaf(h[3],  c0.w, y);
            y = fmaf(h[4],  c1.x, y);
            y = fmaf(h[5],  c1.y, y);
            y = fmaf(h[6],  c1.z, y);
            y = fmaf(h[7],  c1.w, y);
            y = fmaf(h[8],  c2.x, y);
            y = fmaf(h[9],  c2.y, y);
            y = fmaf(h[10], c2.z, y);
            y = fmaf(h[11], c2.w, y);
            y = fmaf(h[12], c3.x, y);
            y = fmaf(h[13], c3.y, y);
            y = fmaf(h[14], c3.z, y);
            y = fmaf(h[15], c3.w, y);
            float z  = fmaf(ash[t], p1z, fmaf(csh[t], p2z, p3z));
            float zs = __fdividef(z, 1.0f + __expf(-z)) * we;
            float outv = fmaf(Dd, xcc, y) * zs;
#pragma unroll
            for (int o = 16; o > 0; o >>= 1)
                outv += __shfl_xor_sync(0xffffffffu, outv, o);
            if (lane == 0) sred[warp][t] = outv;
        }
        dtv = dtn; xcv = xcn;
    }
    __syncthreads();
    if (tid < TT) {
        float s = 0.f;
#pragma unroll
        for (int w = 0; w < 8; w++) s += sred[w][tid];
        g_red[dg * (BB * LL) + b * LL + t0 + tid] = s;
    }
}

// ---------------- K7: combine 4 d-group partials + residual -------------------
__global__ __launch_bounds__(256) void k_fin2(const float* __restrict__ x,
                                              const float* __restrict__ bout,
                                              float* __restrict__ out) {
    int row = blockIdx.x * 256 + threadIdx.x;   // < 16384
    float s = g_red[row] + g_red[BB * LL + row] + g_red[2 * BB * LL + row] +
              g_red[3 * BB * LL + row];
    out[row] = s + bout[0] + x[row];
}

// ---------------- launch ------------------------------------------------------
extern "C" void kernel_launch(void* const* d_in, const int* in_sizes, int n_in,
                              void* d_out, int out_size) {
    const float* x      = (const float*)d_in[0];
    const float* W_in1  = (const float*)d_in[1];
    const float* b_in1  = (const float*)d_in[2];
    const float* ln_g   = (const float*)d_in[3];
    const float* ln_b   = (const float*)d_in[4];
    const float* W_xz   = (const float*)d_in[5];
    const float* conv_w = (const float*)d_in[6];
    const float* conv_b = (const float*)d_in[7];
    const float* W_xp   = (const float*)d_in[8];
    const float* W_dt   = (const float*)d_in[9];
    const float* b_dt   = (const float*)d_in[10];
    const float* A_log  = (const float*)d_in[11];
    const float* D_skip = (const float*)d_in[12];
    const float* W_om   = (const float*)d_in[13];
    const float* W_out  = (const float*)d_in[14];
    const float* b_out  = (const float*)d_in[15];
    float* out = (float*)d_out;

    k_stats<<<1, 512>>>(W_in1, b_in1);
    k_prep<<<164, 256>>>(W_in1, b_in1, ln_g, ln_b, W_xz, W_om, W_out, A_log, x);
    k_xc<<<1024, 256>>>(conv_w, conv_b);
    k_proj<<<256, 256>>>(W_xp);
    k_dt<<<1024, 256>>>(W_dt, b_dt);
    k_scan1<<<1024, 256>>>();
    k_scan2<<<32, 256>>>();
    k_scan3<<<1024, 256>>>(D_skip);
    k_fin2<<<64, 256>>>(x, b_out, out);
}

// round 16
// speedup vs baseline: 1.5598x; 1.5598x over previous
#include <cuda_runtime.h>
#include <cuda_bf16.h>
#include <math.h>

#define BB 8
#define LL 2048
#define DM 512
#define DI 1024
#define DS 16
#define DTR 32
#define CC 32          // time chunks
#define TT 64          // chunk length
#define EPSV 1e-5f

// ---------------- scratch (device globals; no runtime allocation) -------------
__device__ float g_scal[8];                 // mw, mb, mww, mwb, mbb
__device__ int   g_fastA;
__device__ float g_p1[2 * DI];
__device__ float g_p2[2 * DI];
__device__ float g_p3[2 * DI];
__device__ float g_weff[DI];
__device__ float g_A[DI * DS];              // -exp(A_log)
__device__ float g_a[BB * LL];
__device__ float g_c[BB * LL];
__device__ float g_xc[(size_t)BB * DI * LL];   // [b][d][t] conv+silu output
__device__ float g_dtl[BB * LL * DTR];         // [b][t][32] dt low-rank
__device__ float g_Bt[BB * DS * LL];           // [b][s][t]
__device__ float g_Ct[BB * DS * LL];           // [b][s][t]
__device__ float g_dtT[(size_t)BB * DI * LL];  // [b][d][t] softplus(dt)
__device__ float g_hF[(size_t)BB * CC * DI * DS];   // chunk-local final states
__device__ float g_Ssum[BB * CC * DI];              // chunk dt sums
__device__ float g_H[(size_t)BB * CC * DI * DS];    // incoming state per chunk
__device__ float g_red[4 * BB * LL];                // d-group partial sums

// scalar power tree: p[s] = e1^(s+1)
#define POWTREE(p, e1)                                                          \
    {                                                                           \
        p[0] = (e1);  p[1] = p[0] * p[0];  p[2] = p[1] * p[0];                  \
        p[3] = p[1] * p[1];  p[4] = p[3] * p[0];  p[5] = p[3] * p[1];           \
        p[6] = p[3] * p[2];  p[7] = p[3] * p[3];  p[8] = p[7] * p[0];           \
        p[9] = p[7] * p[1];  p[10] = p[7] * p[2]; p[11] = p[7] * p[3];          \
        p[12] = p[7] * p[4]; p[13] = p[7] * p[5]; p[14] = p[7] * p[6];          \
        p[15] = p[7] * p[7];                                                    \
    }

// ---------------- K1: moments of W_in1 / b_in1 --------------------------------
__global__ void k_stats(const float* __restrict__ w, const float* __restrict__ b) {
    __shared__ float sh[5][16];
    int tid = threadIdx.x;               // 512 threads
    float wv = w[tid], bv = b[tid];
    float v[5] = {wv, bv, wv * wv, wv * bv, bv * bv};
#pragma unroll
    for (int j = 0; j < 5; j++) {
#pragma unroll
        for (int o = 16; o > 0; o >>= 1) v[j] += __shfl_xor_sync(0xffffffffu, v[j], o);
    }
    if ((tid & 31) == 0) {
#pragma unroll
        for (int j = 0; j < 5; j++) sh[j][tid >> 5] = v[j];
    }
    if (tid == 0) g_fastA = 1;
    __syncthreads();
    if (tid < 5) {
        float s = 0.f;
#pragma unroll
        for (int k = 0; k < 16; k++) s += sh[tid][k];
        g_scal[tid] = s * (1.0f / DM);
    }
}

// ---------------- K2: p-vectors, w_eff, A, per-token a/c ----------------------
__global__ void k_prep(const float* __restrict__ Win1, const float* __restrict__ bin1,
                       const float* __restrict__ lng,  const float* __restrict__ lnb,
                       const float* __restrict__ Wxz,  const float* __restrict__ Wom,
                       const float* __restrict__ Wout, const float* __restrict__ Alog,
                       const float* __restrict__ x) {
    int idx = blockIdx.x * 256 + threadIdx.x;
    float mw = g_scal[0], mb = g_scal[1], mww = g_scal[2], mwb = g_scal[3], mbb = g_scal[4];
    if (idx < 4 * 2 * DI) {
        int col  = idx >> 2;              // output column 0..2047
        int part = idx & 3;               // d-range split
        float s1 = 0.f, s2 = 0.f, s3 = 0.f;
        for (int d = part * 128; d < part * 128 + 128; d++) {
            float gd = lng[d];
            float u = (Win1[d] - mw) * gd;
            float v = (bin1[d] - mb) * gd;
            float wv = Wxz[d * (2 * DI) + col];
            s1 = fmaf(u, wv, s1);
            s2 = fmaf(v, wv, s2);
            s3 = fmaf(lnb[d], wv, s3);
        }
        s1 += __shfl_xor_sync(0xffffffffu, s1, 1); s1 += __shfl_xor_sync(0xffffffffu, s1, 2);
        s2 += __shfl_xor_sync(0xffffffffu, s2, 1); s2 += __shfl_xor_sync(0xffffffffu, s2, 2);
        s3 += __shfl_xor_sync(0xffffffffu, s3, 1); s3 += __shfl_xor_sync(0xffffffffu, s3, 2);
        if (part == 0) { g_p1[col] = s1; g_p2[col] = s2; g_p3[col] = s3; }
    } else if (idx < 8192 + DI) {
        int j = idx - 8192;
        float s = 0.f;
        for (int m = 0; m < DM; m++) s = fmaf(Wom[j * DM + m], Wout[m], s);
        g_weff[j] = s;
    } else if (idx < 8192 + DI + DI * DS) {
        int i2 = idx - 8192 - DI;
        float av = -expf(Alog[i2]);
        g_A[i2] = av;
        int s = i2 & (DS - 1);
        float expect = -(float)(s + 1);
        if (fabsf(av - expect) > 1e-4f * (float)(s + 1)) atomicAnd(&g_fastA, 0);
    } else if (idx < 8192 + DI + DI * DS + BB * LL) {
        int i2 = idx - 8192 - DI - DI * DS;
        float xv = x[i2];
        float varw = mww - mw * mw;
        float cwb  = mwb - mw * mb;
        float varb = mbb - mb * mb;
        float var  = fmaf(xv * xv, varw, fmaf(2.0f * xv, cwb, varb));
        float s    = rsqrtf(var + EPSV);
        g_a[i2] = xv * s;
        g_c[i2] = s;
    }
}

// ---------------- K3: conv + silu -> xc (32B buffered stores) -----------------
__global__ __launch_bounds__(256) void k_xc(const float* __restrict__ convw,
                                            const float* __restrict__ convb) {
    int bx = blockIdx.x;                      // 1024 blocks
    int b   = bx >> 7;
    int rem = bx & 127;
    int t0  = (rem >> 2) * 64;
    int d   = (rem & 3) * 256 + threadIdx.x;

    __shared__ float shA[67], shC[67];
    if (threadIdx.x < 67) {
        int gt = t0 - 3 + (int)threadIdx.x;
        shA[threadIdx.x] = (gt >= 0) ? g_a[b * LL + gt] : 0.f;
        shC[threadIdx.x] = (gt >= 0) ? g_c[b * LL + gt] : 0.f;
    }
    float p1d = g_p1[d], p2d = g_p2[d], p3d = g_p3[d];
    float cw0 = convw[d * 4 + 0], cw1 = convw[d * 4 + 1];
    float cw2 = convw[d * 4 + 2], cw3 = convw[d * 4 + 3];
    float cb = convb[d];
    float cwsum = cw0 + cw1 + cw2 + cw3;
    __syncthreads();

    float* xop = g_xc + ((size_t)(b * DI + d)) * LL + t0;
    float xb[8];
#pragma unroll 8
    for (int tt = 0; tt < 64; tt++) {
        int t = t0 + tt;
        float a0 = shA[tt], a1 = shA[tt + 1], a2 = shA[tt + 2], a3 = shA[tt + 3];
        float c0 = shC[tt], c1 = shC[tt + 1], c2 = shC[tt + 2], c3 = shC[tt + 3];
        float sa = fmaf(a0, cw0, fmaf(a1, cw1, fmaf(a2, cw2, a3 * cw3)));
        float sc = fmaf(c0, cw0, fmaf(c1, cw1, fmaf(c2, cw2, c3 * cw3)));
        float sw;
        if (t >= 3) sw = cwsum;
        else { sw = cw3; if (t >= 1) sw += cw2; if (t >= 2) sw += cw1; }
        float pre = fmaf(p1d, sa, fmaf(p2d, sc, fmaf(p3d, sw, cb)));
        xb[tt & 7] = __fdividef(pre, 1.0f + __expf(-pre));
        if ((tt & 7) == 7) {
            *(float4*)(xop + tt - 7) = make_float4(xb[0], xb[1], xb[2], xb[3]);
            *(float4*)(xop + tt - 3) = make_float4(xb[4], xb[5], xb[6], xb[7]);
        }
    }
}

// ---------------- K4: xc @ W_xp (double-buffered tiles) -----------------------
__global__ __launch_bounds__(256) void k_proj(const float* __restrict__ Wxp) {
    int blk = blockIdx.x;                    // 256 blocks
    int b  = blk >> 5;
    int t0 = (blk & 31) * 64;
    __shared__ float At[2][32][68];
    __shared__ float Bt_[2][32][64];
    int tid = threadIdx.x;
    int tx = tid & 15, ty = tid >> 4;
    float acc[4][4];
#pragma unroll
    for (int i = 0; i < 4; i++)
#pragma unroll
        for (int j = 0; j < 4; j++) acc[i][j] = 0.f;

    int akk0 = tid >> 4,          at40 = tid & 15;
    int akk1 = (tid + 256) >> 4,  at41 = tid & 15;
    const size_t xcb = (size_t)(b * DI) * LL + t0;

    float4 ra0 = *(const float4*)(g_xc + xcb + (size_t)(akk0)*LL + at40 * 4);
    float4 ra1 = *(const float4*)(g_xc + xcb + (size_t)(akk1)*LL + at41 * 4);
    float4 rb0 = *(const float4*)(Wxp + (size_t)(akk0)*64 + at40 * 4);
    float4 rb1 = *(const float4*)(Wxp + (size_t)(akk1)*64 + at41 * 4);
    *(float4*)&At[0][akk0][at40 * 4] = ra0;
    *(float4*)&At[0][akk1][at41 * 4] = ra1;
    *(float4*)&Bt_[0][akk0][at40 * 4] = rb0;
    *(float4*)&Bt_[0][akk1][at41 * 4] = rb1;
    __syncthreads();

    for (int kt = 0; kt < 32; kt++) {
        int cur = kt & 1;
        if (kt < 31) {
            int k0 = (kt + 1) * 32;
            ra0 = *(const float4*)(g_xc + xcb + (size_t)(k0 + akk0) * LL + at40 * 4);
            ra1 = *(const float4*)(g_xc + xcb + (size_t)(k0 + akk1) * LL + at41 * 4);
            rb0 = *(const float4*)(Wxp + (size_t)(k0 + akk0) * 64 + at40 * 4);
            rb1 = *(const float4*)(Wxp + (size_t)(k0 + akk1) * 64 + at41 * 4);
        }
#pragma unroll
        for (int kk = 0; kk < 32; kk++) {
            float4 bv = *(float4*)&Bt_[cur][kk][tx * 4];
            float4 av = *(float4*)&At[cur][kk][ty * 4];
            acc[0][0] = fmaf(av.x, bv.x, acc[0][0]);
            acc[0][1] = fmaf(av.x, bv.y, acc[0][1]);
            acc[0][2] = fmaf(av.x, bv.z, acc[0][2]);
            acc[0][3] = fmaf(av.x, bv.w, acc[0][3]);
            acc[1][0] = fmaf(av.y, bv.x, acc[1][0]);
            acc[1][1] = fmaf(av.y, bv.y, acc[1][1]);
            acc[1][2] = fmaf(av.y, bv.z, acc[1][2]);
            acc[1][3] = fmaf(av.y, bv.w, acc[1][3]);
            acc[2][0] = fmaf(av.z, bv.x, acc[2][0]);
            acc[2][1] = fmaf(av.z, bv.y, acc[2][1]);
            acc[2][2] = fmaf(av.z, bv.z, acc[2][2]);
            acc[2][3] = fmaf(av.z, bv.w, acc[2][3]);
            acc[3][0] = fmaf(av.w, bv.x, acc[3][0]);
            acc[3][1] = fmaf(av.w, bv.y, acc[3][1]);
            acc[3][2] = fmaf(av.w, bv.z, acc[3][2]);
            acc[3][3] = fmaf(av.w, bv.w, acc[3][3]);
        }
        if (kt < 31) {
            int nxt = cur ^ 1;
            *(float4*)&At[nxt][akk0][at40 * 4] = ra0;
            *(float4*)&At[nxt][akk1][at41 * 4] = ra1;
            *(float4*)&Bt_[nxt][akk0][at40 * 4] = rb0;
            *(float4*)&Bt_[nxt][akk1][at41 * 4] = rb1;
        }
        __syncthreads();
    }
#pragma unroll
    for (int i = 0; i < 4; i++) {
        int t = t0 + ty * 4 + i;
        if (tx < 8) {
            *(float4*)(g_dtl + ((size_t)(b * LL + t)) * DTR + tx * 4) =
                make_float4(acc[i][0], acc[i][1], acc[i][2], acc[i][3]);
        } else {
#pragma unroll
            for (int j = 0; j < 4; j++) {
                int n = tx * 4 + j;
                if (n < 48) g_Bt[((size_t)(b * DS + n - 32)) * LL + t] = acc[i][j];
                else        g_Ct[((size_t)(b * DS + n - 48)) * LL + t] = acc[i][j];
            }
        }
    }
}

// ---------------- K5: softplus(dt_low @ W_dt + b_dt) -> dtT [b][d][t] ---------
__global__ __launch_bounds__(256) void k_dt(const float* __restrict__ Wdt,
                                            const float* __restrict__ bdt) {
    int blk = blockIdx.x;                    // 1024 blocks
    int b   = blk >> 7;
    int rem = blk & 127;
    int t0  = (rem >> 2) * 64;
    int d   = (rem & 3) * 256 + threadIdx.x;
    __shared__ float sh[64][32];
    const float4* src = (const float4*)(g_dtl + ((size_t)(b * LL + t0)) * DTR);
    float4* dst = (float4*)&sh[0][0];
    for (int i = threadIdx.x; i < 512; i += 256) dst[i] = src[i];
    float wreg[32];
#pragma unroll
    for (int k = 0; k < 32; k++) wreg[k] = Wdt[(size_t)k * DI + d];
    float bd = bdt[d];
    __syncthreads();
    float* op = g_dtT + ((size_t)(b * DI + d)) * LL + t0;
    float buf[8];
#pragma unroll 8
    for (int tt = 0; tt < 64; tt++) {
        float acc = bd;
#pragma unroll
        for (int k4 = 0; k4 < 8; k4++) {
            float4 v = *(const float4*)&sh[tt][k4 * 4];
            acc = fmaf(v.x, wreg[k4 * 4 + 0], acc);
            acc = fmaf(v.y, wreg[k4 * 4 + 1], acc);
            acc = fmaf(v.z, wreg[k4 * 4 + 2], acc);
            acc = fmaf(v.w, wreg[k4 * 4 + 3], acc);
        }
        buf[tt & 7] = (acc > 20.0f) ? acc : log1pf(__expf(acc));
        if ((tt & 7) == 7) {
            *(float4*)(op + tt - 7) = make_float4(buf[0], buf[1], buf[2], buf[3]);
            *(float4*)(op + tt - 3) = make_float4(buf[4], buf[5], buf[6], buf[7]);
        }
    }
}

// ---------------- K6a: chunk-local scan (prefetched stream) -------------------
__global__ __launch_bounds__(256) void k_scan1(void) {
    int blk = blockIdx.x;                // 1024 = b(8) x c(32) x dg(4)
    int b  = blk >> 7;
    int c  = (blk >> 2) & 31;
    int dg = blk & 3;
    int tid = threadIdx.x;
    int d  = dg * 256 + tid;
    int t0 = c * TT;

    __shared__ float Bs[TT * DS];        // [t][s]
    for (int i = tid; i < TT * DS; i += 256) {
        int s = i >> 6, t = i & 63;
        Bs[t * DS + s] = g_Bt[((size_t)b * DS + s) * LL + t0 + t];
    }
    __syncthreads();

    const float4* dtp = (const float4*)(g_dtT + ((size_t)b * DI + d) * LL + t0);
    const float4* xcp = (const float4*)(g_xc  + ((size_t)b * DI + d) * LL + t0);
    int fast = g_fastA;
    float Areg[16];
    if (!fast) {
#pragma unroll
        for (int s = 0; s < 16; s++) Areg[s] = g_A[d * DS + s];
    }
    float h[16];
#pragma unroll
    for (int s = 0; s < 16; s++) h[s] = 0.f;
    float S = 0.f;

    float4 dtv = dtp[0], xcv = xcp[0];
#pragma unroll 4
    for (int q = 0; q < TT / 4; q++) {
        float4 dtn, xcn;
        if (q < TT / 4 - 1) { dtn = dtp[q + 1]; xcn = xcp[q + 1]; }
#pragma unroll
        for (int u = 0; u < 4; u++) {
            float dtc = (u == 0) ? dtv.x : (u == 1) ? dtv.y : (u == 2) ? dtv.z : dtv.w;
            float xcc = (u == 0) ? xcv.x : (u == 1) ? xcv.y : (u == 2) ? xcv.z : xcv.w;
            int t = q * 4 + u;
            S += dtc;
            float dx = dtc * xcc;
            float p[16];
            if (fast) {
                float e1 = __expf(-dtc);
                POWTREE(p, e1)
            } else {
#pragma unroll
                for (int s = 0; s < 16; s++) p[s] = __expf(dtc * Areg[s]);
            }
            const float4* bp = (const float4*)&Bs[t * DS];
            float4 b0 = bp[0], b1 = bp[1], b2 = bp[2], b3 = bp[3];
            h[0]  = fmaf(h[0],  p[0],  dx * b0.x);
            h[1]  = fmaf(h[1],  p[1],  dx * b0.y);
            h[2]  = fmaf(h[2],  p[2],  dx * b0.z);
            h[3]  = fmaf(h[3],  p[3],  dx * b0.w);
            h[4]  = fmaf(h[4],  p[4],  dx * b1.x);
            h[5]  = fmaf(h[5],  p[5],  dx * b1.y);
            h[6]  = fmaf(h[6],  p[6],  dx * b1.z);
            h[7]  = fmaf(h[7],  p[7],  dx * b1.w);
            h[8]  = fmaf(h[8],  p[8],  dx * b2.x);
            h[9]  = fmaf(h[9],  p[9],  dx * b2.y);
            h[10] = fmaf(h[10], p[10], dx * b2.z);
            h[11] = fmaf(h[11], p[11], dx * b2.w);
            h[12] = fmaf(h[12], p[12], dx * b3.x);
            h[13] = fmaf(h[13], p[13], dx * b3.y);
            h[14] = fmaf(h[14], p[14], dx * b3.z);
            h[15] = fmaf(h[15], p[15], dx * b3.w);
        }
        dtv = dtn; xcv = xcn;
    }
    float* o = g_hF + (((size_t)b * CC + c) * DI + d) * DS;
    *(float4*)(o + 0)  = make_float4(h[0], h[1], h[2], h[3]);
    *(float4*)(o + 4)  = make_float4(h[4], h[5], h[6], h[7]);
    *(float4*)(o + 8)  = make_float4(h[8], h[9], h[10], h[11]);
    *(float4*)(o + 12) = make_float4(h[12], h[13], h[14], h[15]);
    g_Ssum[((size_t)b * CC + c) * DI + d] = S;
}

// ---------------- K6b: propagate states across chunks ------------------------
__global__ __launch_bounds__(256) void k_scan2(void) {
    int idx = blockIdx.x * 256 + threadIdx.x;     // < 8192
    int b = idx >> 10;
    int d = idx & (DI - 1);
    int fast = g_fastA;
    float Areg[16];
    if (!fast) {
#pragma unroll
        for (int s = 0; s < 16; s++) Areg[s] = g_A[d * DS + s];
    }
    float H[16];
#pragma unroll
    for (int s = 0; s < 16; s++) H[s] = 0.f;
#pragma unroll 4
    for (int c = 0; c < CC; c++) {
        float* o = g_H + (((size_t)b * CC + c) * DI + d) * DS;
        *(float4*)(o + 0)  = make_float4(H[0], H[1], H[2], H[3]);
        *(float4*)(o + 4)  = make_float4(H[4], H[5], H[6], H[7]);
        *(float4*)(o + 8)  = make_float4(H[8], H[9], H[10], H[11]);
        *(float4*)(o + 12) = make_float4(H[12], H[13], H[14], H[15]);
        float S = g_Ssum[((size_t)b * CC + c) * DI + d];
        float p[16];
        if (fast) {
            float e1 = __expf(-S);
            POWTREE(p, e1)
        } else {
#pragma unroll
            for (int s = 0; s < 16; s++) p[s] = __expf(S * Areg[s]);
        }
        const float* f = g_hF + (((size_t)b * CC + c) * DI + d) * DS;
        float4 f0 = *(const float4*)(f + 0), f1 = *(const float4*)(f + 4);
        float4 f2 = *(const float4*)(f + 8), f3 = *(const float4*)(f + 12);
        H[0]  = fmaf(H[0],  p[0],  f0.x);  H[1]  = fmaf(H[1],  p[1],  f0.y);
        H[2]  = fmaf(H[2],  p[2],  f0.z);  H[3]  = fmaf(H[3],  p[3],  f0.w);
        H[4]  = fmaf(H[4],  p[4],  f1.x);  H[5]  = fmaf(H[5],  p[5],  f1.y);
        H[6]  = fmaf(H[6],  p[6],  f1.z);  H[7]  = fmaf(H[7],  p[7],  f1.w);
        H[8]  = fmaf(H[8],  p[8],  f2.x);  H[9]  = fmaf(H[9],  p[9],  f2.y);
        H[10] = fmaf(H[10], p[10], f2.z);  H[11] = fmaf(H[11], p[11], f2.w);
        H[12] = fmaf(H[12], p[12], f3.x);  H[13] = fmaf(H[13], p[13], f3.y);
        H[14] = fmaf(H[14], p[14], f3.z);  H[15] = fmaf(H[15], p[15], f3.w);
    }
}

// ---------------- K6c: full scan + gate + fused d-reduction (prefetched) ------
__global__ __launch_bounds__(256) void k_scan3(const float* __restrict__ Dskip) {
    int blk = blockIdx.x;                // 1024 = b(8) x c(32) x dg(4)
    int b  = blk >> 7;
    int c  = (blk >> 2) & 31;
    int dg = blk & 3;
    int tid = threadIdx.x;
    int d  = dg * 256 + tid;
    int t0 = c * TT;
    int lane = tid & 31;
    int warp = tid >> 5;

    __shared__ float Bs[TT * DS];
    __shared__ float Cs[TT * DS];
    __shared__ float ash[TT], csh[TT];
    __shared__ float sred[8][TT];
    for (int i = tid; i < 2 * TT * DS; i += 256) {
        int half = i >> 10;               // 0 = B, 1 = C
        int j = i & 1023;
        int s = j >> 6, t = j & 63;
        float v = half ? g_Ct[((size_t)b * DS + s) * LL + t0 + t]
                       : g_Bt[((size_t)b * DS + s) * LL + t0 + t];
        (half ? Cs : Bs)[t * DS + s] = v;
    }
    if (tid < TT) {
        ash[tid] = g_a[b * LL + t0 + tid];
        csh[tid] = g_c[b * LL + t0 + tid];
    }
    __syncthreads();

    const float4* dtp = (const float4*)(g_dtT + ((size_t)b * DI + d) * LL + t0);
    const float4* xcp = (const float4*)(g_xc  + ((size_t)b * DI + d) * LL + t0);
    int fast = g_fastA;
    float Areg[16];
    if (!fast) {
#pragma unroll
        for (int s = 0; s < 16; s++) Areg[s] = g_A[d * DS + s];
    }
    float p1z = g_p1[DI + d], p2z = g_p2[DI + d], p3z = g_p3[DI + d];
    float we = g_weff[d];
    float Dd = Dskip[d];
    const float* Hp = g_H + (((size_t)b * CC + c) * DI + d) * DS;
    float4 H0 = *(const float4*)(Hp + 0), H1 = *(const float4*)(Hp + 4);
    float4 H2 = *(const float4*)(Hp + 8), H3 = *(const float4*)(Hp + 12);
    float h[16] = {H0.x, H0.y, H0.z, H0.w, H1.x, H1.y, H1.z, H1.w,
                   H2.x, H2.y, H2.z, H2.w, H3.x, H3.y, H3.z, H3.w};

    float4 dtv = dtp[0], xcv = xcp[0];
#pragma unroll 2
    for (int q = 0; q < TT / 4; q++) {
        float4 dtn, xcn;
        if (q < TT / 4 - 1) { dtn = dtp[q + 1]; xcn = xcp[q + 1]; }
#pragma unroll
        for (int u = 0; u < 4; u++) {
            float dtc = (u == 0) ? dtv.x : (u == 1) ? dtv.y : (u == 2) ? dtv.z : dtv.w;
            float xcc = (u == 0) ? xcv.x : (u == 1) ? xcv.y : (u == 2) ? xcv.z : xcv.w;
            int t = q * 4 + u;
            float dx = dtc * xcc;
            float p[16];
            if (fast) {
                float e1 = __expf(-dtc);
                POWTREE(p, e1)
            } else {
#pragma unroll
                for (int s = 0; s < 16; s++) p[s] = __expf(dtc * Areg[s]);
            }
            const float4* bp = (const float4*)&Bs[t * DS];
            const float4* cp = (const float4*)&Cs[t * DS];
            float4 b0 = bp[0], b1 = bp[1], b2 = bp[2], b3 = bp[3];
            float4 c0 = cp[0], c1 = cp[1], c2 = cp[2], c3 = cp[3];
            h[0]  = fmaf(h[0],  p[0],  dx * b0.x);
            h[1]  = fmaf(h[1],  p[1],  dx * b0.y);
            h[2]  = fmaf(h[2],  p[2],  dx * b0.z);
            h[3]  = fmaf(h[3],  p[3],  dx * b0.w);
            h[4]  = fmaf(h[4],  p[4],  dx * b1.x);
            h[5]  = fmaf(h[5],  p[5],  dx * b1.y);
            h[6]  = fmaf(h[6],  p[6],  dx * b1.z);
            h[7]  = fmaf(h[7],  p[7],  dx * b1.w);
            h[8]  = fmaf(h[8],  p[8],  dx * b2.x);
            h[9]  = fmaf(h[9],  p[9],  dx * b2.y);
            h[10] = fmaf(h[10], p[10], dx * b2.z);
            h[11] = fmaf(h[11], p[11], dx * b2.w);
            h[12] = fmaf(h[12], p[12], dx * b3.x);
            h[13] = fmaf(h[13], p[13], dx * b3.y);
            h[14] = fmaf(h[14], p[14], dx * b3.z);
            h[15] = fmaf(h[15], p[15], dx * b3.w);
            float y = h[0] * c0.x;
            y = fmaf(h[1],  c0.y, y);
            y = fmaf(h[2],  c0.z, y);
            y = fmaf(h[3],  c0.w, y);
            y = fmaf(h[4],  c1.x, y);
            y = fmaf(h[5],  c1.y, y);
            y = fmaf(h[6],  c1.z, y);
            y = fmaf(h[7],  c1.w, y);
            y = fmaf(h[8],  c2.x, y);
            y = fmaf(h[9],  c2.y, y);
            y = fmaf(h[10], c2.z, y);
            y = fmaf(h[11], c2.w, y);
            y = fmaf(h[12], c3.x, y);
            y = fmaf(h[13], c3.y, y);
            y = fmaf(h[14], c3.z, y);
            y = fmaf(h[15], c3.w, y);
            float z  = fmaf(ash[t], p1z, fmaf(csh[t], p2z, p3z));
            float zs = __fdividef(z, 1.0f + __expf(-z)) * we;
            float outv = fmaf(Dd, xcc, y) * zs;
#pragma unroll
            for (int o = 16; o > 0; o >>= 1)
                outv += __shfl_xor_sync(0xffffffffu, outv, o);
            if (lane == 0) sred[warp][t] = outv;
        }
        dtv = dtn; xcv = xcn;
    }
    __syncthreads();
    if (tid < TT) {
        float s = 0.f;
#pragma unroll
        for (int w = 0; w < 8; w++) s += sred[w][tid];
        g_red[dg * (BB * LL) + b * LL + t0 + tid] = s;
    }
}

// ---------------- K7: combine 4 d-group partials + residual -------------------
__global__ __launch_bounds__(256) void k_fin2(const float* __restrict__ x,
                                              const float* __restrict__ bout,
                                              float* __restrict__ out) {
    int row = blockIdx.x * 256 + threadIdx.x;   // < 16384
    float s = g_red[row] + g_red[BB * LL + row] + g_red[2 * BB * LL + row] +
              g_red[3 * BB * LL + row];
    out[row] = s + bout[0] + x[row];
}

// ---------------- launch ------------------------------------------------------
extern "C" void kernel_launch(void* const* d_in, const int* in_sizes, int n_in,
                              void* d_out, int out_size) {
    const float* x      = (const float*)d_in[0];
    const float* W_in1  = (const float*)d_in[1];
    const float* b_in1  = (const float*)d_in[2];
    const float* ln_g   = (const float*)d_in[3];
    const float* ln_b   = (const float*)d_in[4];
    const float* W_xz   = (const float*)d_in[5];
    const float* conv_w = (const float*)d_in[6];
    const float* conv_b = (const float*)d_in[7];
    const float* W_xp   = (const float*)d_in[8];
    const float* W_dt   = (const float*)d_in[9];
    const float* b_dt   = (const float*)d_in[10];
    const float* A_log  = (const float*)d_in[11];
    const float* D_skip = (const float*)d_in[12];
    const float* W_om   = (const float*)d_in[13];
    const float* W_out  = (const float*)d_in[14];
    const float* b_out  = (const float*)d_in[15];
    float* out = (float*)d_out;

    k_stats<<<1, 512>>>(W_in1, b_in1);
    k_prep<<<164, 256>>>(W_in1, b_in1, ln_g, ln_b, W_xz, W_om, W_out, A_log, x);
    k_xc<<<1024, 256>>>(conv_w, conv_b);
    k_proj<<<256, 256>>>(W_xp);
    k_dt<<<1024, 256>>>(W_dt, b_dt);
    k_scan1<<<1024, 256>>>();
    k_scan2<<<32, 256>>>();
    k_scan3<<<1024, 256>>>(D_skip);
    k_fin2<<<64, 256>>>(x, b_out, out);
}

// round 17
// speedup vs baseline: 1.5601x; 1.0002x over previous
#include <cuda_runtime.h>
#include <cuda_bf16.h>
#include <math.h>

#define BB 8
#define LL 2048
#define DM 512
#define DI 1024
#define DS 16
#define DTR 32
#define CC 32          // time chunks
#define TT 64          // chunk length
#define EPSV 1e-5f

// ---------------- scratch (device globals; no runtime allocation) -------------
__device__ float g_scal[8];                 // mw, mb, mww, mwb, mbb
__device__ int   g_fastA;
__device__ float g_p1[2 * DI];
__device__ float g_p2[2 * DI];
__device__ float g_p3[2 * DI];
__device__ float g_weff[DI];
__device__ float g_A[DI * DS];              // -exp(A_log)
__device__ float g_a[BB * LL];
__device__ float g_c[BB * LL];
__device__ float g_xc[(size_t)BB * DI * LL];   // [b][d][t] conv+silu output
__device__ float g_dtl[BB * LL * DTR];         // [b][t][32] dt low-rank
__device__ float g_Bt[BB * DS * LL];           // [b][s][t]
__device__ float g_Ct[BB * DS * LL];           // [b][s][t]
__device__ float g_dtT[(size_t)BB * DI * LL];  // [b][d][t] softplus(dt)
__device__ float g_hF[(size_t)BB * CC * DI * DS];   // chunk-local final states
__device__ float g_Ssum[BB * CC * DI];              // chunk dt sums
__device__ float g_H[(size_t)BB * CC * DI * DS];    // incoming state per chunk
__device__ float g_red[4 * BB * LL];                // d-group partial sums

// scalar power tree: p[s] = e1^(s+1)
#define POWTREE(p, e1)                                                          \
    {                                                                           \
        p[0] = (e1);  p[1] = p[0] * p[0];  p[2] = p[1] * p[0];                  \
        p[3] = p[1] * p[1];  p[4] = p[3] * p[0];  p[5] = p[3] * p[1];           \
        p[6] = p[3] * p[2];  p[7] = p[3] * p[3];  p[8] = p[7] * p[0];           \
        p[9] = p[7] * p[1];  p[10] = p[7] * p[2]; p[11] = p[7] * p[3];          \
        p[12] = p[7] * p[4]; p[13] = p[7] * p[5]; p[14] = p[7] * p[6];          \
        p[15] = p[7] * p[7];                                                    \
    }

// ---------------- K1: moments of W_in1 / b_in1 --------------------------------
__global__ void k_stats(const float* __restrict__ w, const float* __restrict__ b) {
    __shared__ float sh[5][16];
    int tid = threadIdx.x;               // 512 threads
    float wv = w[tid], bv = b[tid];
    float v[5] = {wv, bv, wv * wv, wv * bv, bv * bv};
#pragma unroll
    for (int j = 0; j < 5; j++) {
#pragma unroll
        for (int o = 16; o > 0; o >>= 1) v[j] += __shfl_xor_sync(0xffffffffu, v[j], o);
    }
    if ((tid & 31) == 0) {
#pragma unroll
        for (int j = 0; j < 5; j++) sh[j][tid >> 5] = v[j];
    }
    if (tid == 0) g_fastA = 1;
    __syncthreads();
    if (tid < 5) {
        float s = 0.f;
#pragma unroll
        for (int k = 0; k < 16; k++) s += sh[tid][k];
        g_scal[tid] = s * (1.0f / DM);
    }
}

// ---------------- K2: p-vectors, w_eff, A, per-token a/c ----------------------
__global__ void k_prep(const float* __restrict__ Win1, const float* __restrict__ bin1,
                       const float* __restrict__ lng,  const float* __restrict__ lnb,
                       const float* __restrict__ Wxz,  const float* __restrict__ Wom,
                       const float* __restrict__ Wout, const float* __restrict__ Alog,
                       const float* __restrict__ x) {
    int idx = blockIdx.x * 256 + threadIdx.x;
    float mw = g_scal[0], mb = g_scal[1], mww = g_scal[2], mwb = g_scal[3], mbb = g_scal[4];
    if (idx < 4 * 2 * DI) {
        int col  = idx >> 2;              // output column 0..2047
        int part = idx & 3;               // d-range split
        float s1 = 0.f, s2 = 0.f, s3 = 0.f;
        for (int d = part * 128; d < part * 128 + 128; d++) {
            float gd = lng[d];
            float u = (Win1[d] - mw) * gd;
            float v = (bin1[d] - mb) * gd;
            float wv = Wxz[d * (2 * DI) + col];
            s1 = fmaf(u, wv, s1);
            s2 = fmaf(v, wv, s2);
            s3 = fmaf(lnb[d], wv, s3);
        }
        s1 += __shfl_xor_sync(0xffffffffu, s1, 1); s1 += __shfl_xor_sync(0xffffffffu, s1, 2);
        s2 += __shfl_xor_sync(0xffffffffu, s2, 1); s2 += __shfl_xor_sync(0xffffffffu, s2, 2);
        s3 += __shfl_xor_sync(0xffffffffu, s3, 1); s3 += __shfl_xor_sync(0xffffffffu, s3, 2);
        if (part == 0) { g_p1[col] = s1; g_p2[col] = s2; g_p3[col] = s3; }
    } else if (idx < 8192 + DI) {
        int j = idx - 8192;
        float s = 0.f;
        for (int m = 0; m < DM; m++) s = fmaf(Wom[j * DM + m], Wout[m], s);
        g_weff[j] = s;
    } else if (idx < 8192 + DI + DI * DS) {
        int i2 = idx - 8192 - DI;
        float av = -expf(Alog[i2]);
        g_A[i2] = av;
        int s = i2 & (DS - 1);
        float expect = -(float)(s + 1);
        if (fabsf(av - expect) > 1e-4f * (float)(s + 1)) atomicAnd(&g_fastA, 0);
    } else if (idx < 8192 + DI + DI * DS + BB * LL) {
        int i2 = idx - 8192 - DI - DI * DS;
        float xv = x[i2];
        float varw = mww - mw * mw;
        float cwb  = mwb - mw * mb;
        float varb = mbb - mb * mb;
        float var  = fmaf(xv * xv, varw, fmaf(2.0f * xv, cwb, varb));
        float s    = rsqrtf(var + EPSV);
        g_a[i2] = xv * s;
        g_c[i2] = s;
    }
}

// ---------------- K3: conv + silu -> xc (32B buffered stores) -----------------
__global__ __launch_bounds__(256) void k_xc(const float* __restrict__ convw,
                                            const float* __restrict__ convb) {
    int bx = blockIdx.x;                      // 1024 blocks
    int b   = bx >> 7;
    int rem = bx & 127;
    int t0  = (rem >> 2) * 64;
    int d   = (rem & 3) * 256 + threadIdx.x;

    __shared__ float shA[67], shC[67];
    if (threadIdx.x < 67) {
        int gt = t0 - 3 + (int)threadIdx.x;
        shA[threadIdx.x] = (gt >= 0) ? g_a[b * LL + gt] : 0.f;
        shC[threadIdx.x] = (gt >= 0) ? g_c[b * LL + gt] : 0.f;
    }
    float p1d = g_p1[d], p2d = g_p2[d], p3d = g_p3[d];
    float cw0 = convw[d * 4 + 0], cw1 = convw[d * 4 + 1];
    float cw2 = convw[d * 4 + 2], cw3 = convw[d * 4 + 3];
    float cb = convb[d];
    float cwsum = cw0 + cw1 + cw2 + cw3;
    __syncthreads();

    float* xop = g_xc + ((size_t)(b * DI + d)) * LL + t0;
    float xb[8];
#pragma unroll 8
    for (int tt = 0; tt < 64; tt++) {
        int t = t0 + tt;
        float a0 = shA[tt], a1 = shA[tt + 1], a2 = shA[tt + 2], a3 = shA[tt + 3];
        float c0 = shC[tt], c1 = shC[tt + 1], c2 = shC[tt + 2], c3 = shC[tt + 3];
        float sa = fmaf(a0, cw0, fmaf(a1, cw1, fmaf(a2, cw2, a3 * cw3)));
        float sc = fmaf(c0, cw0, fmaf(c1, cw1, fmaf(c2, cw2, c3 * cw3)));
        float sw;
        if (t >= 3) sw = cwsum;
        else { sw = cw3; if (t >= 1) sw += cw2; if (t >= 2) sw += cw1; }
        float pre = fmaf(p1d, sa, fmaf(p2d, sc, fmaf(p3d, sw, cb)));
        xb[tt & 7] = __fdividef(pre, 1.0f + __expf(-pre));
        if ((tt & 7) == 7) {
            *(float4*)(xop + tt - 7) = make_float4(xb[0], xb[1], xb[2], xb[3]);
            *(float4*)(xop + tt - 3) = make_float4(xb[4], xb[5], xb[6], xb[7]);
        }
    }
}

// ---------------- K4: xc @ W_xp (double-buffered tiles) -----------------------
__global__ __launch_bounds__(256) void k_proj(const float* __restrict__ Wxp) {
    int blk = blockIdx.x;                    // 256 blocks
    int b  = blk >> 5;
    int t0 = (blk & 31) * 64;
    __shared__ float At[2][32][68];
    __shared__ float Bt_[2][32][64];
    int tid = threadIdx.x;
    int tx = tid & 15, ty = tid >> 4;
    float acc[4][4];
#pragma unroll
    for (int i = 0; i < 4; i++)
#pragma unroll
        for (int j = 0; j < 4; j++) acc[i][j] = 0.f;

    int akk0 = tid >> 4,          at40 = tid & 15;
    int akk1 = (tid + 256) >> 4,  at41 = tid & 15;
    const size_t xcb = (size_t)(b * DI) * LL + t0;

    float4 ra0 = *(const float4*)(g_xc + xcb + (size_t)(akk0)*LL + at40 * 4);
    float4 ra1 = *(const float4*)(g_xc + xcb + (size_t)(akk1)*LL + at41 * 4);
    float4 rb0 = *(const float4*)(Wxp + (size_t)(akk0)*64 + at40 * 4);
    float4 rb1 = *(const float4*)(Wxp + (size_t)(akk1)*64 + at41 * 4);
    *(float4*)&At[0][akk0][at40 * 4] = ra0;
    *(float4*)&At[0][akk1][at41 * 4] = ra1;
    *(float4*)&Bt_[0][akk0][at40 * 4] = rb0;
    *(float4*)&Bt_[0][akk1][at41 * 4] = rb1;
    __syncthreads();

    for (int kt = 0; kt < 32; kt++) {
        int cur = kt & 1;
        if (kt < 31) {
            int k0 = (kt + 1) * 32;
            ra0 = *(const float4*)(g_xc + xcb + (size_t)(k0 + akk0) * LL + at40 * 4);
            ra1 = *(const float4*)(g_xc + xcb + (size_t)(k0 + akk1) * LL + at41 * 4);
            rb0 = *(const float4*)(Wxp + (size_t)(k0 + akk0) * 64 + at40 * 4);
            rb1 = *(const float4*)(Wxp + (size_t)(k0 + akk1) * 64 + at41 * 4);
        }
#pragma unroll
        for (int kk = 0; kk < 32; kk++) {
            float4 bv = *(float4*)&Bt_[cur][kk][tx * 4];
            float4 av = *(float4*)&At[cur][kk][ty * 4];
            acc[0][0] = fmaf(av.x, bv.x, acc[0][0]);
            acc[0][1] = fmaf(av.x, bv.y, acc[0][1]);
            acc[0][2] = fmaf(av.x, bv.z, acc[0][2]);
            acc[0][3] = fmaf(av.x, bv.w, acc[0][3]);
            acc[1][0] = fmaf(av.y, bv.x, acc[1][0]);
            acc[1][1] = fmaf(av.y, bv.y, acc[1][1]);
            acc[1][2] = fmaf(av.y, bv.z, acc[1][2]);
            acc[1][3] = fmaf(av.y, bv.w, acc[1][3]);
            acc[2][0] = fmaf(av.z, bv.x, acc[2][0]);
            acc[2][1] = fmaf(av.z, bv.y, acc[2][1]);
            acc[2][2] = fmaf(av.z, bv.z, acc[2][2]);
            acc[2][3] = fmaf(av.z, bv.w, acc[2][3]);
            acc[3][0] = fmaf(av.w, bv.x, acc[3][0]);
            acc[3][1] = fmaf(av.w, bv.y, acc[3][1]);
            acc[3][2] = fmaf(av.w, bv.z, acc[3][2]);
            acc[3][3] = fmaf(av.w, bv.w, acc[3][3]);
        }
        if (kt < 31) {
            int nxt = cur ^ 1;
            *(float4*)&At[nxt][akk0][at40 * 4] = ra0;
            *(float4*)&At[nxt][akk1][at41 * 4] = ra1;
            *(float4*)&Bt_[nxt][akk0][at40 * 4] = rb0;
            *(float4*)&Bt_[nxt][akk1][at41 * 4] = rb1;
        }
        __syncthreads();
    }
#pragma unroll
    for (int i = 0; i < 4; i++) {
        int t = t0 + ty * 4 + i;
        if (tx < 8) {
            *(float4*)(g_dtl + ((size_t)(b * LL + t)) * DTR + tx * 4) =
                make_float4(acc[i][0], acc[i][1], acc[i][2], acc[i][3]);
        } else {
#pragma unroll
            for (int j = 0; j < 4; j++) {
                int n = tx * 4 + j;
                if (n < 48) g_Bt[((size_t)(b * DS + n - 32)) * LL + t] = acc[i][j];
                else        g_Ct[((size_t)(b * DS + n - 48)) * LL + t] = acc[i][j];
            }
        }
    }
}

// ---------------- K5: softplus(dt_low @ W_dt + b_dt) -> dtT [b][d][t] ---------
__global__ __launch_bounds__(256) void k_dt(const float* __restrict__ Wdt,
                                            const float* __restrict__ bdt) {
    int blk = blockIdx.x;                    // 1024 blocks
    int b   = blk >> 7;
    int rem = blk & 127;
    int t0  = (rem >> 2) * 64;
    int d   = (rem & 3) * 256 + threadIdx.x;
    __shared__ float sh[64][32];
    const float4* src = (const float4*)(g_dtl + ((size_t)(b * LL + t0)) * DTR);
    float4* dst = (float4*)&sh[0][0];
    for (int i = threadIdx.x; i < 512; i += 256) dst[i] = src[i];
    float wreg[32];
#pragma unroll
    for (int k = 0; k < 32; k++) wreg[k] = Wdt[(size_t)k * DI + d];
    float bd = bdt[d];
    __syncthreads();
    float* op = g_dtT + ((size_t)(b * DI + d)) * LL + t0;
    float buf[8];
#pragma unroll 8
    for (int tt = 0; tt < 64; tt++) {
        float acc = bd;
#pragma unroll
        for (int k4 = 0; k4 < 8; k4++) {
            float4 v = *(const float4*)&sh[tt][k4 * 4];
            acc = fmaf(v.x, wreg[k4 * 4 + 0], acc);
            acc = fmaf(v.y, wreg[k4 * 4 + 1], acc);
            acc = fmaf(v.z, wreg[k4 * 4 + 2], acc);
            acc = fmaf(v.w, wreg[k4 * 4 + 3], acc);
        }
        buf[tt & 7] = (acc > 20.0f) ? acc : log1pf(__expf(acc));
        if ((tt & 7) == 7) {
            *(float4*)(op + tt - 7) = make_float4(buf[0], buf[1], buf[2], buf[3]);
            *(float4*)(op + tt - 3) = make_float4(buf[4], buf[5], buf[6], buf[7]);
        }
    }
}

// ---------------- K6a: chunk-local scan (prefetched stream) -------------------
__global__ __launch_bounds__(256) void k_scan1(void) {
    int blk = blockIdx.x;                // 1024 = b(8) x c(32) x dg(4)
    int b  = blk >> 7;
    int c  = (blk >> 2) & 31;
    int dg = blk & 3;
    int tid = threadIdx.x;
    int d  = dg * 256 + tid;
    int t0 = c * TT;

    __shared__ float Bs[TT * DS];        // [t][s]
    for (int i = tid; i < TT * DS; i += 256) {
        int s = i >> 6, t = i & 63;
        Bs[t * DS + s] = g_Bt[((size_t)b * DS + s) * LL + t0 + t];
    }
    __syncthreads();

    const float4* dtp = (const float4*)(g_dtT + ((size_t)b * DI + d) * LL + t0);
    const float4* xcp = (const float4*)(g_xc  + ((size_t)b * DI + d) * LL + t0);
    int fast = g_fastA;
    float Areg[16];
    if (!fast) {
#pragma unroll
        for (int s = 0; s < 16; s++) Areg[s] = g_A[d * DS + s];
    }
    float h[16];
#pragma unroll
    for (int s = 0; s < 16; s++) h[s] = 0.f;
    float S = 0.f;

    float4 dtv = dtp[0], xcv = xcp[0];
#pragma unroll 4
    for (int q = 0; q < TT / 4; q++) {
        float4 dtn, xcn;
        if (q < TT / 4 - 1) { dtn = dtp[q + 1]; xcn = xcp[q + 1]; }
#pragma unroll
        for (int u = 0; u < 4; u++) {
            float dtc = (u == 0) ? dtv.x : (u == 1) ? dtv.y : (u == 2) ? dtv.z : dtv.w;
            float xcc = (u == 0) ? xcv.x : (u == 1) ? xcv.y : (u == 2) ? xcv.z : xcv.w;
            int t = q * 4 + u;
            S += dtc;
            float dx = dtc * xcc;
            float p[16];
            if (fast) {
                float e1 = __expf(-dtc);
                POWTREE(p, e1)
            } else {
#pragma unroll
                for (int s = 0; s < 16; s++) p[s] = __expf(dtc * Areg[s]);
            }
            const float4* bp = (const float4*)&Bs[t * DS];
            float4 b0 = bp[0], b1 = bp[1], b2 = bp[2], b3 = bp[3];
            h[0]  = fmaf(h[0],  p[0],  dx * b0.x);
            h[1]  = fmaf(h[1],  p[1],  dx * b0.y);
            h[2]  = fmaf(h[2],  p[2],  dx * b0.z);
            h[3]  = fmaf(h[3],  p[3],  dx * b0.w);
            h[4]  = fmaf(h[4],  p[4],  dx * b1.x);
            h[5]  = fmaf(h[5],  p[5],  dx * b1.y);
            h[6]  = fmaf(h[6],  p[6],  dx * b1.z);
            h[7]  = fmaf(h[7],  p[7],  dx * b1.w);
            h[8]  = fmaf(h[8],  p[8],  dx * b2.x);
            h[9]  = fmaf(h[9],  p[9],  dx * b2.y);
            h[10] = fmaf(h[10], p[10], dx * b2.z);
            h[11] = fmaf(h[11], p[11], dx * b2.w);
            h[12] = fmaf(h[12], p[12], dx * b3.x);
            h[13] = fmaf(h[13], p[13], dx * b3.y);
            h[14] = fmaf(h[14], p[14], dx * b3.z);
            h[15] = fmaf(h[15], p[15], dx * b3.w);
        }
        dtv = dtn; xcv = xcn;
    }
    float* o = g_hF + (((size_t)b * CC + c) * DI + d) * DS;
    *(float4*)(o + 0)  = make_float4(h[0], h[1], h[2], h[3]);
    *(float4*)(o + 4)  = make_float4(h[4], h[5], h[6], h[7]);
    *(float4*)(o + 8)  = make_float4(h[8], h[9], h[10], h[11]);
    *(float4*)(o + 12) = make_float4(h[12], h[13], h[14], h[15]);
    g_Ssum[((size_t)b * CC + c) * DI + d] = S;
}

// ---------------- K6b: propagate states across chunks ------------------------
__global__ __launch_bounds__(256) void k_scan2(void) {
    int idx = blockIdx.x * 256 + threadIdx.x;     // < 8192
    int b = idx >> 10;
    int d = idx & (DI - 1);
    int fast = g_fastA;
    float Areg[16];
    if (!fast) {
#pragma unroll
        for (int s = 0; s < 16; s++) Areg[s] = g_A[d * DS + s];
    }
    float H[16];
#pragma unroll
    for (int s = 0; s < 16; s++) H[s] = 0.f;
#pragma unroll 4
    for (int c = 0; c < CC; c++) {
        float* o = g_H + (((size_t)b * CC + c) * DI + d) * DS;
        *(float4*)(o + 0)  = make_float4(H[0], H[1], H[2], H[3]);
        *(float4*)(o + 4)  = make_float4(H[4], H[5], H[6], H[7]);
        *(float4*)(o + 8)  = make_float4(H[8], H[9], H[10], H[11]);
        *(float4*)(o + 12) = make_float4(H[12], H[13], H[14], H[15]);
        float S = g_Ssum[((size_t)b * CC + c) * DI + d];
        float p[16];
        if (fast) {
            float e1 = __expf(-S);
            POWTREE(p, e1)
        } else {
#pragma unroll
            for (int s = 0; s < 16; s++) p[s] = __expf(S * Areg[s]);
        }
        const float* f = g_hF + (((size_t)b * CC + c) * DI + d) * DS;
        float4 f0 = *(const float4*)(f + 0), f1 = *(const float4*)(f + 4);
        float4 f2 = *(const float4*)(f + 8), f3 = *(const float4*)(f + 12);
        H[0]  = fmaf(H[0],  p[0],  f0.x);  H[1]  = fmaf(H[1],  p[1],  f0.y);
        H[2]  = fmaf(H[2],  p[2],  f0.z);  H[3]  = fmaf(H[3],  p[3],  f0.w);
        H[4]  = fmaf(H[4],  p[4],  f1.x);  H[5]  = fmaf(H[5],  p[5],  f1.y);
        H[6]  = fmaf(H[6],  p[6],  f1.z);  H[7]  = fmaf(H[7],  p[7],  f1.w);
        H[8]  = fmaf(H[8],  p[8],  f2.x);  H[9]  = fmaf(H[9],  p[9],  f2.y);
        H[10] = fmaf(H[10], p[10], f2.z);  H[11] = fmaf(H[11], p[11], f2.w);
        H[12] = fmaf(H[12], p[12], f3.x);  H[13] = fmaf(H[13], p[13], f3.y);
        H[14] = fmaf(H[14], p[14], f3.z);  H[15] = fmaf(H[15], p[15], f3.w);
    }
}

// ---------------- K6c: full scan + gate + fused d-reduction (prefetched) ------
__global__ __launch_bounds__(256) void k_scan3(const float* __restrict__ Dskip) {
    int blk = blockIdx.x;                // 1024 = b(8) x c(32) x dg(4)
    int b  = blk >> 7;
    int c  = (blk >> 2) & 31;
    int dg = blk & 3;
    int tid = threadIdx.x;
    int d  = dg * 256 + tid;
    int t0 = c * TT;
    int lane = tid & 31;
    int warp = tid >> 5;

    __shared__ float Bs[TT * DS];
    __shared__ float Cs[TT * DS];
    __shared__ float ash[TT], csh[TT];
    __shared__ float sred[8][TT];
    for (int i = tid; i < 2 * TT * DS; i += 256) {
        int half = i >> 10;               // 0 = B, 1 = C
        int j = i & 1023;
        int s = j >> 6, t = j & 63;
        float v = half ? g_Ct[((size_t)b * DS + s) * LL + t0 + t]
                       : g_Bt[((size_t)b * DS + s) * LL + t0 + t];
        (half ? Cs : Bs)[t * DS + s] = v;
    }
    if (tid < TT) {
        ash[tid] = g_a[b * LL + t0 + tid];
        csh[tid] = g_c[b * LL + t0 + tid];
    }
    __syncthreads();

    const float4* dtp = (const float4*)(g_dtT + ((size_t)b * DI + d) * LL + t0);
    const float4* xcp = (const float4*)(g_xc  + ((size_t)b * DI + d) * LL + t0);
    int fast = g_fastA;
    float Areg[16];
    if (!fast) {
#pragma unroll
        for (int s = 0; s < 16; s++) Areg[s] = g_A[d * DS + s];
    }
    float p1z = g_p1[DI + d], p2z = g_p2[DI + d], p3z = g_p3[DI + d];
    float we = g_weff[d];
    float Dd = Dskip[d];
    const float* Hp = g_H + (((size_t)b * CC + c) * DI + d) * DS;
    float4 H0 = *(const float4*)(Hp + 0), H1 = *(const float4*)(Hp + 4);
    float4 H2 = *(const float4*)(Hp + 8), H3 = *(const float4*)(Hp + 12);
    float h[16] = {H0.x, H0.y, H0.z, H0.w, H1.x, H1.y, H1.z, H1.w,
                   H2.x, H2.y, H2.z, H2.w, H3.x, H3.y, H3.z, H3.w};

    float4 dtv = dtp[0], xcv = xcp[0];
#pragma unroll 2
    for (int q = 0; q < TT / 4; q++) {
        float4 dtn, xcn;
        if (q < TT / 4 - 1) { dtn = dtp[q + 1]; xcn = xcp[q + 1]; }
#pragma unroll
        for (int u = 0; u < 4; u++) {
            float dtc = (u == 0) ? dtv.x : (u == 1) ? dtv.y : (u == 2) ? dtv.z : dtv.w;
            float xcc = (u == 0) ? xcv.x : (u == 1) ? xcv.y : (u == 2) ? xcv.z : xcv.w;
            int t = q * 4 + u;
            float dx = dtc * xcc;
            float p[16];
            if (fast) {
                float e1 = __expf(-dtc);
                POWTREE(p, e1)
            } else {
#pragma unroll
                for (int s = 0; s < 16; s++) p[s] = __expf(dtc * Areg[s]);
            }
            const float4* bp = (const float4*)&Bs[t * DS];
            const float4* cp = (const float4*)&Cs[t * DS];
            float4 b0 = bp[0], b1 = bp[1], b2 = bp[2], b3 = bp[3];
            float4 c0 = cp[0], c1 = cp[1], c2 = cp[2], c3 = cp[3];
            h[0]  = fmaf(h[0],  p[0],  dx * b0.x);
            h[1]  = fmaf(h[1],  p[1],  dx * b0.y);
            h[2]  = fmaf(h[2],  p[2],  dx * b0.z);
            h[3]  = fmaf(h[3],  p[3],  dx * b0.w);
            h[4]  = fmaf(h[4],  p[4],  dx * b1.x);
            h[5]  = fmaf(h[5],  p[5],  dx * b1.y);
            h[6]  = fmaf(h[6],  p[6],  dx * b1.z);
            h[7]  = fmaf(h[7],  p[7],  dx * b1.w);
            h[8]  = fmaf(h[8],  p[8],  dx * b2.x);
            h[9]  = fmaf(h[9],  p[9],  dx * b2.y);
            h[10] = fmaf(h[10], p[10], dx * b2.z);
            h[11] = fmaf(h[11], p[11], dx * b2.w);
            h[12] = fmaf(h[12], p[12], dx * b3.x);
            h[13] = fmaf(h[13], p[13], dx * b3.y);
            h[14] = fmaf(h[14], p[14], dx * b3.z);
            h[15] = fmaf(h[15], p[15], dx * b3.w);
            float y = h[0] * c0.x;
            y = fmaf(h[1],  c0.y, y);
            y = fmaf(h[2],  c0.z, y);
            y = fmaf(h[3],  c0.w, y);
            y = fmaf(h[4],  c1.x, y);
            y = fmaf(h[5],  c1.y, y);
            y = fmaf(h[6],  c1.z, y);
            y = fmaf(h[7],  c1.w, y);
            y = fmaf(h[8],  c2.x, y);
            y = fmaf(h[9],  c2.y, y);
            y = fmaf(h[10], c2.z, y);
            y = fmaf(h[11], c2.w, y);
            y = fmaf(h[12], c3.x, y);
            y = fmaf(h[13], c3.y, y);
            y = fmaf(h[14], c3.z, y);
            y = fmaf(h[15], c3.w, y);
            float z  = fmaf(ash[t], p1z, fmaf(csh[t], p2z, p3z));
            float zs = __fdividef(z, 1.0f + __expf(-z)) * we;
            float outv = fmaf(Dd, xcc, y) * zs;
#pragma unroll
            for (int o = 16; o > 0; o >>= 1)
                outv += __shfl_xor_sync(0xffffffffu, outv, o);
            if (lane == 0) sred[warp][t] = outv;
        }
        dtv = dtn; xcv = xcn;
    }
    __syncthreads();
    if (tid < TT) {
        float s = 0.f;
#pragma unroll
        for (int w = 0; w < 8; w++) s += sred[w][tid];
        g_red[dg * (BB * LL) + b * LL + t0 + tid] = s;
    }
}

// ---------------- K7: combine 4 d-group partials + residual -------------------
__global__ __launch_bounds__(256) void k_fin2(const float* __restrict__ x,
                                              const float* __restrict__ bout,
                                              float* __restrict__ out) {
    int row = blockIdx.x * 256 + threadIdx.x;   // < 16384
    float s = g_red[row] + g_red[BB * LL + row] + g_red[2 * BB * LL + row] +
              g_red[3 * BB * LL + row];
    out[row] = s + bout[0] + x[row];
}

// ---------------- launch ------------------------------------------------------
extern "C" void kernel_launch(void* const* d_in, const int* in_sizes, int n_in,
                              void* d_out, int out_size) {
    const float* x      = (const float*)d_in[0];
    const float* W_in1  = (const float*)d_in[1];
    const float* b_in1  = (const float*)d_in[2];
    const float* ln_g   = (const float*)d_in[3];
    const float* ln_b   = (const float*)d_in[4];
    const float* W_xz   = (const float*)d_in[5];
    const float* conv_w = (const float*)d_in[6];
    const float* conv_b = (const float*)d_in[7];
    const float* W_xp   = (const float*)d_in[8];
    const float* W_dt   = (const float*)d_in[9];
    const float* b_dt   = (const float*)d_in[10];
    const float* A_log  = (const float*)d_in[11];
    const float* D_skip = (const float*)d_in[12];
    const float* W_om   = (const float*)d_in[13];
    const float* W_out  = (const float*)d_in[14];
    const float* b_out  = (const float*)d_in[15];
    float* out = (float*)d_out;

    k_stats<<<1, 512>>>(W_in1, b_in1);
    k_prep<<<164, 256>>>(W_in1, b_in1, ln_g, ln_b, W_xz, W_om, W_out, A_log, x);
    k_xc<<<1024, 256>>>(conv_w, conv_b);
    k_proj<<<256, 256>>>(W_xp);
    k_dt<<<1024, 256>>>(W_dt, b_dt);
    k_scan1<<<1024, 256>>>();
    k_scan2<<<32, 256>>>();
    k_scan3<<<1024, 256>>>(D_skip);
    k_fin2<<<64, 256>>>(x, b_out, out);
}